// round 3
// baseline (speedup 1.0000x reference)
#include <cuda_runtime.h>
#include <cuda_bf16.h>
#include <cstdint>

// Problem constants
#define LSZ 6400      // L = 80*80
#define CDIM 64
#define WDIM 80
#define TI 128
#define TJ 128

// Output layout (float32), total 448000:
//   [0      .. 12800)  mkpts0  [L][2]
//   [12800  .. 25600)  mkpts1  [L][2]
//   [25600  .. 32000)  mask_v  [L]
//   [32000  .. 38400)  score   [L]
//   [38400  .. 448000) sa_ir_up [640][640]

__device__ unsigned long long g_rowpack[LSZ];
__device__ unsigned int       g_colmax[LSZ];

__device__ __forceinline__ unsigned fenc(float f) {
    unsigned u = __float_as_uint(f);
    return (u & 0x80000000u) ? ~u : (u | 0x80000000u);
}
__device__ __forceinline__ float fdec(unsigned e) {
    return __uint_as_float((e & 0x80000000u) ? (e ^ 0x80000000u) : ~e);
}

__global__ void init_kernel() {
    int i = blockIdx.x * blockDim.x + threadIdx.x;
    if (i < LSZ) { g_rowpack[i] = 0ull; g_colmax[i] = 0u; }
}

// Fused GEMM + mask + row-argmax + col-max.
// A = feat_reg_vi [C][L], B = feat_reg_ir [C][L] (channel-major).
__global__ __launch_bounds__(256)
void semla_gemm_kernel(const float* __restrict__ A, const float* __restrict__ B,
                       const float* __restrict__ saV, const float* __restrict__ saI) {
    __shared__ float As[32][TI];
    __shared__ float Bs[32][TJ];
    __shared__ unsigned scol[TJ];
    __shared__ float ssaV[TI];
    __shared__ float ssaI[TJ];

    const int tid = threadIdx.x;
    const int tx = tid & 15;        // col group (8 cols each)
    const int ty = tid >> 4;        // row group (8 rows each)
    const int i0 = blockIdx.y * TI;
    const int j0 = blockIdx.x * TJ;

    if (tid < TI) {
        scol[tid] = 0u;
        ssaV[tid] = saV[i0 + tid];
        ssaI[tid] = saI[j0 + tid];
    }

    float acc[8][8];
    #pragma unroll
    for (int r = 0; r < 8; ++r)
        #pragma unroll
        for (int c = 0; c < 8; ++c) acc[r][c] = 0.f;

    for (int kc = 0; kc < CDIM; kc += 32) {
        __syncthreads();
        // load 32x128 of A and B: 1024 float4 each, 4 per thread
        #pragma unroll
        for (int t = 0; t < 4; ++t) {
            int li = tid + t * 256;         // 0..1023
            int cc = li >> 5;               // /32 -> k row
            int x4 = li & 31;               // float4 index in row
            *(float4*)&As[cc][x4 * 4] = *(const float4*)&A[(kc + cc) * LSZ + i0 + x4 * 4];
            *(float4*)&Bs[cc][x4 * 4] = *(const float4*)&B[(kc + cc) * LSZ + j0 + x4 * 4];
        }
        __syncthreads();

        #pragma unroll 8
        for (int k = 0; k < 32; ++k) {
            float a[8], b[8];
            *(float4*)(a)     = *(float4*)&As[k][ty * 8];
            *(float4*)(a + 4) = *(float4*)&As[k][ty * 8 + 4];
            *(float4*)(b)     = *(float4*)&Bs[k][tx * 8];
            *(float4*)(b + 4) = *(float4*)&Bs[k][tx * 8 + 4];
            #pragma unroll
            for (int r = 0; r < 8; ++r)
                #pragma unroll
                for (int c = 0; c < 8; ++c)
                    acc[r][c] += a[r] * b[c];
        }
    }

    // ---- epilogue: scale, validity mask, row argmax, col max ----
    const float scale = 0.15625f;    // 1/(sqrt(64)*sqrt(64)*0.1) = 1/6.4 (exact)
    const float NEGV = -1e9f;

    #pragma unroll
    for (int r = 0; r < 8; ++r) {
        const int gi = i0 + ty * 8 + r;
        const bool vr = ssaV[ty * 8 + r] > 0.f;
        unsigned best = 0u; int bj = j0;
        #pragma unroll
        for (int c = 0; c < 8; ++c) {
            const bool vc = ssaI[tx * 8 + c] > 0.f;
            float v = (vr && vc) ? acc[r][c] * scale : NEGV;
            acc[r][c] = v;                      // reuse for col pass
            unsigned e = fenc(v);
            if (e > best) { best = e; bj = j0 + tx * 8 + c; }
        }
        unsigned long long pk = ((unsigned long long)best << 32) | (unsigned)bj;
        // reduce across the 16 threads (tx=0..15) sharing this row; xor<=8 stays in group
        #pragma unroll
        for (int off = 8; off; off >>= 1) {
            unsigned long long o = __shfl_xor_sync(0xFFFFFFFFu, pk, off);
            if (o > pk) pk = o;
        }
        if (tx == 0) atomicMax(&g_rowpack[gi], pk);
    }

    #pragma unroll
    for (int c = 0; c < 8; ++c) {
        unsigned m = 0u;
        #pragma unroll
        for (int r = 0; r < 8; ++r) {
            unsigned e = fenc(acc[r][c]);
            if (e > m) m = e;
        }
        atomicMax(&scol[tx * 8 + c], m);
    }
    __syncthreads();
    if (tid < TJ) atomicMax(&g_colmax[j0 + tid], scol[tid]);
}

__global__ void finalize_kernel(float* __restrict__ out) {
    int i = blockIdx.x * blockDim.x + threadIdx.x;
    if (i >= LSZ) return;
    // mkpts0
    out[2 * i]     = (float)((i % WDIM) * 8);
    out[2 * i + 1] = (float)((i / WDIM) * 8);

    unsigned long long p = g_rowpack[i];
    unsigned enc = (unsigned)(p >> 32);
    int aj = (int)(p & 0xFFFFFFFFull);
    float rm = fdec(enc);
    bool mv = (rm > 0.f) && (enc == g_colmax[aj]);
    int j = mv ? aj : 0;

    out[12800 + 2 * i]     = (float)((j % WDIM) * 8);
    out[12800 + 2 * i + 1] = (float)((j / WDIM) * 8);
    out[25600 + i] = mv ? 1.f : 0.f;
    out[32000 + i] = mv ? rm : 0.f;   // conf[i, all_j] * mask_v
}

__global__ void upsample_kernel(const float* __restrict__ sa, float* __restrict__ out) {
    int idx = blockIdx.x * blockDim.x + threadIdx.x;
    if (idx >= 640 * 640) return;
    int ox = idx % 640, oy = idx / 640;
    float fy = (float)(oy * 79) / 639.0f;
    float fx = (float)(ox * 79) / 639.0f;
    int y0 = (int)floorf(fy); int y1 = min(y0 + 1, 79); float wy = fy - (float)y0;
    int x0 = (int)floorf(fx); int x1 = min(x0 + 1, 79); float wx = fx - (float)x0;
    float v00 = sa[y0 * WDIM + x0], v01 = sa[y0 * WDIM + x1];
    float v10 = sa[y1 * WDIM + x0], v11 = sa[y1 * WDIM + x1];
    float r0 = v00 * (1.f - wy) + v10 * wy;   // interp along H first (matches ref)
    float r1 = v01 * (1.f - wy) + v11 * wy;
    out[38400 + idx] = r0 * (1.f - wx) + r1 * wx;
}

extern "C" void kernel_launch(void* const* d_in, const int* in_sizes, int n_in,
                              void* d_out, int out_size) {
    const float* feat_reg_vi = (const float*)d_in[0];  // [1,64,80,80]
    const float* feat_reg_ir = (const float*)d_in[1];  // [1,64,80,80]
    const float* feat_sa_vi  = (const float*)d_in[2];  // [1,1,80,80]
    const float* feat_sa_ir  = (const float*)d_in[3];  // [1,1,80,80]
    float* out = (float*)d_out;

    init_kernel<<<(LSZ + 255) / 256, 256>>>();
    semla_gemm_kernel<<<dim3(LSZ / TJ, LSZ / TI), 256>>>(feat_reg_vi, feat_reg_ir,
                                                         feat_sa_vi, feat_sa_ir);
    finalize_kernel<<<(LSZ + 255) / 256, 256>>>(out);
    upsample_kernel<<<(640 * 640 + 255) / 256, 256>>>(feat_sa_ir, out);
}